// round 15
// baseline (speedup 1.0000x reference)
#include <cuda_runtime.h>
#include <cuda_fp16.h>
#include <cstdint>

// ---------------------------------------------------------------------------
// S4D kernel materialization via raw mma.sync (HMMA.16816), sm_100-safe.
//   K[d,l] = 2*Re( sum_n Cc[d,n] * exp(dtA[d,n] * l) ),  D=512, N=32, L=8192
//
// Split l = 64*m + b:  K[d,64m+b] = sum_k A[m,k]*B[b,k]  (real GEMM, K=64)
//   A[m, n] = Re(u), A[m,32+n] = Im(u),  u = 2*Cc_n * exp(dtA_n*64m)
//   B[b, n] = Re(w), B[b,32+n] = -Im(w), w = exp(dtA_n*b)
//
// Round 15 = Round 12 + M-split: 2 CTAs per d (64 M-rows each) -> 1024 CTAs,
// 13.6 KB smem, launch_bounds(128,7) -> 7 CTAs/SM = 28 warps/SM, single
// wave. Per-warp work ~55-60% of R12 (1 mtile instead of 2: shorter A-build
// chain, half the MMAs, half the stores). A fragments in registers, B via
// smem tables, direct scattered stores (R13/14 proved staging hurts).
// ---------------------------------------------------------------------------

#define D_MODEL 512
#define SEQ     8192
#define NST     32
#define TROW    34                    // float2 per table row (pad)
#define BROW32  36                    // u32 per B row (72 halves = 144 B)

// ---- helpers ---------------------------------------------------------------
__device__ __forceinline__ float2 cmul(float2 a, float2 b) {
    return make_float2(a.x * b.x - a.y * b.y, a.x * b.y + a.y * b.x);
}
// exp(scale*(dtAr + i*dtAi)), fp32 Cody-Waite mod-2pi (validated R7/R11/R12).
__device__ __forceinline__ float2 cexp_fast(float dtAr, float dtAi, float scale) {
    float e  = __expf(scale * dtAr);
    float mi = scale * dtAi;
    float k  = rintf(mi * 0.15915494f);
    float th = fmaf(-k, 6.2831855f, mi);
    th = fmaf(k, 1.7484556e-7f, th);
    float s, c;
    __sincosf(th, &s, &c);
    return make_float2(e * c, e * s);
}
// pack two fp32 -> half2 (v0 in low half)
__device__ __forceinline__ uint32_t pkh2(float v0, float v1) {
    __half2 h = __halves2half2(__float2half_rn(v0), __float2half_rn(v1));
    return *(uint32_t*)&h;
}
__device__ __forceinline__ void mma16816(float* acc, const uint32_t* a,
                                         const uint32_t* b) {
    asm volatile(
        "mma.sync.aligned.m16n8k16.row.col.f32.f16.f16.f32 "
        "{%0,%1,%2,%3}, {%4,%5,%6,%7}, {%8,%9}, {%0,%1,%2,%3};"
        : "+f"(acc[0]), "+f"(acc[1]), "+f"(acc[2]), "+f"(acc[3])
        : "r"(a[0]), "r"(a[1]), "r"(a[2]), "r"(a[3]), "r"(b[0]), "r"(b[1]));
}

// ---------------------------------------------------------------------------
__global__ void __launch_bounds__(128, 7)
s4d_mma_kernel(const float* __restrict__ log_dt,
               const float* __restrict__ log_A_real,
               const float* __restrict__ A_imag,
               const float2* __restrict__ C,
               float* __restrict__ out)
{
    __shared__ float2   tR[16 * TROW];        // rows 0-7: r^i ; 8-15: r^(8j)
    __shared__ uint32_t Bs[64 * BROW32];      // B fp16 [b][72 halves]

    const int d     = blockIdx.x >> 1;
    const int mhalf = blockIdx.x & 1;
    const int tid   = threadIdx.x;
    const int w     = tid >> 5;
    const int l     = tid & 31;
    const int q     = l & 3;
    const int g     = l >> 2;

    // ---- per-lane-n constants (lane l owns state n = l) --------------------
    int i = d * NST + l;
    float dt   = __expf(log_dt[d]);
    float Ar   = -__expf(log_A_real[i]);
    float Ai   = A_imag[i];
    float dtAr = Ar * dt;
    float dtAi = Ai * dt;

    // discretized C with final 2x folded in (fast intrinsics; |dtAi|<=0.314)
    float er = __expf(dtAr);
    float sn, cs;
    __sincosf(dtAi, &sn, &cs);
    float Er = er * cs - 1.0f, Ei = er * sn;
    float ar8 = Ar + 1e-8f;
    float inv = 1.0f / (ar8 * ar8 + Ai * Ai);
    float qr = (Er * ar8 + Ei * Ai) * inv;
    float qi = (Ei * ar8 - Er * Ai) * inv;
    float2 Cv = C[i];
    float Ccr = 2.0f * (Cv.x * qr - Cv.y * qi);
    float Cci = 2.0f * (Cv.x * qi + Cv.y * qr);
    float2 r512 = cexp_fast(dtAr, dtAi, 512.0f);

    // ---- Phase 1: tR tables (16 rows; warp w builds rows 4w..4w+3) ---------
#pragma unroll
    for (int rr = 0; rr < 4; rr++) {
        int row = 4 * w + rr;
        float scale = (row < 8) ? (float)row : (float)(8 * (row - 8));
        tR[row * TROW + l] = cexp_fast(dtAr, dtAi, scale);
    }
    __syncthreads();

    // ---- Phase 2: B in smem (b = tid>>1, 8 n2-units each) ------------------
    {
        int b  = tid >> 1;
        int h0 = (tid & 1) * 8;
        const float4* sa = (const float4*)(tR + (b & 7) * TROW);
        const float4* sb = (const float4*)(tR + (8 + (b >> 3)) * TROW);
#pragma unroll
        for (int n2i = 0; n2i < 8; n2i++) {
            int n2 = h0 + n2i;
            float4 a = sa[n2], p = sb[n2];
            float2 w0 = cmul(make_float2(a.x, a.y), make_float2(p.x, p.y));
            float2 w1 = cmul(make_float2(a.z, a.w), make_float2(p.z, p.w));
            Bs[b * BROW32 + n2]      = pkh2(w0.x, w1.x);    // Re  (k = 2n2,2n2+1)
            Bs[b * BROW32 + 16 + n2] = pkh2(-w0.y, -w1.y);  // -Im (k = 32+2n2,..)
        }
    }

    // ---- Phase 3 (overlapped with B wait): A fragments in registers --------
    // Warp w owns ONE mtile: global rows m = 64*mhalf + 16w + {g, g+8}.
    // Thread elements: k-cols {2q,2q+1,2q+8,2q+9}+16s.
    uint32_t Afr[4][4];                      // [kstep][reg]
    const int  m1 = 64 * mhalf + 16 * w + g;
    const float fm = (float)(64 * m1);
#pragma unroll
    for (int p = 0; p < 4; p++) {
        int n0 = 2 * q + 8 * (p & 1) + 16 * (p >> 1);
        float uRe[2][2], uIm[2][2];
#pragma unroll
        for (int e = 0; e < 2; e++) {
            int nn = n0 + e;
            float dar = __shfl_sync(0xffffffffu, dtAr, nn);
            float dai = __shfl_sync(0xffffffffu, dtAi, nn);
            float ccr = __shfl_sync(0xffffffffu, Ccr, nn);
            float cci = __shfl_sync(0xffffffffu, Cci, nn);
            float r5r = __shfl_sync(0xffffffffu, r512.x, nn);
            float r5i = __shfl_sync(0xffffffffu, r512.y, nn);
            float2 x  = cexp_fast(dar, dai, fm);            // r^(64*m1)
            float2 u1 = cmul(make_float2(ccr, cci), x);     // row g
            float2 u2 = cmul(u1, make_float2(r5r, r5i));    // row g+8
            uRe[e][0] = u1.x; uIm[e][0] = u1.y;
            uRe[e][1] = u2.x; uIm[e][1] = u2.y;
        }
        int s_re = p >> 1;          // kstep for Re (s=0,1); Im at s_re+2
        int ab   = 2 * (p & 1);     // reg pair offset (k 2q vs 2q+8)
        Afr[s_re][ab + 0]     = pkh2(uRe[0][0], uRe[1][0]);   // row g
        Afr[s_re][ab + 1]     = pkh2(uRe[0][1], uRe[1][1]);   // row g+8
        Afr[s_re + 2][ab + 0] = pkh2(uIm[0][0], uIm[1][0]);
        Afr[s_re + 2][ab + 1] = pkh2(uIm[0][1], uIm[1][1]);
    }
    __syncthreads();                 // B ready

    // ---- Phase 4: MMA + direct scattered stores (fire-and-forget) ----------
    // b-frag LDS word = 36*(8bt+g) + 8s + q -> bank (4g+q+8s)%32: no conflict.
    float* od0 = out + (size_t)d * SEQ + (size_t)m1 * 64 + 2 * q;
#pragma unroll
    for (int bt = 0; bt < 8; bt++) {
        uint32_t Bfr[4][2];
#pragma unroll
        for (int s = 0; s < 4; s++) {
            const uint32_t* brow = Bs + (8 * bt + g) * BROW32 + 8 * s + q;
            Bfr[s][0] = brow[0];
            Bfr[s][1] = brow[4];
        }
        float acc[4] = {0.f, 0.f, 0.f, 0.f};
#pragma unroll
        for (int s = 0; s < 4; s++) mma16816(acc, Afr[s], Bfr[s]);
        // c0,c1 -> (row m1, cols 8bt+2q,+1); c2,c3 -> row m1+8
        float* o = od0 + 8 * bt;
        *(float2*)(o)          = make_float2(acc[0], acc[1]);
        *(float2*)(o + 8 * 64) = make_float2(acc[2], acc[3]);
    }
}

// ---------------------------------------------------------------------------
extern "C" void kernel_launch(void* const* d_in, const int* in_sizes, int n_in,
                              void* d_out, int out_size)
{
    const float*  log_dt     = (const float*)d_in[0];
    const float*  log_A_real = (const float*)d_in[1];
    const float*  A_imag     = (const float*)d_in[2];
    const float2* C          = (const float2*)d_in[3];
    float* out = (float*)d_out;

    s4d_mma_kernel<<<2 * D_MODEL, 128>>>(log_dt, log_A_real, A_imag, C, out);
}

// round 16
// speedup vs baseline: 1.1063x; 1.1063x over previous
#include <cuda_runtime.h>
#include <cuda_fp16.h>
#include <cstdint>

// ---------------------------------------------------------------------------
// S4D kernel materialization via raw mma.sync (HMMA.16816), sm_100-safe.
//   K[d,l] = 2*Re( sum_n Cc[d,n] * exp(dtA[d,n] * l) ),  D=512, N=32, L=8192
//
// Split l = 64*m + b:  K[d,64m+b] = sum_k A[m,k]*B[b,k]  (real GEMM, K=64)
//   A[m, n] = Re(u), A[m,32+n] = Im(u),  u = 2*Cc_n * exp(dtA_n*64m)
//   B[b, n] = Re(w), B[b,32+n] = -Im(w), w = exp(dtA_n*b)
//
// Round 16 = Round 12 chassis with MIO instruction count halved (~228 ->
// ~110 per warp):
//   - A-build per-n constants via tiny smem table (12 LDS, broadcast) instead
//     of 48 SHFLs; Cc discretization computed by warp 0 only.
//   - Bs stored in mma-fragment word order (pos = 8s+2q+h) with row stride
//     40 words: b-frag loads become 32 conflict-free LDS.64 (was 64 LDS.32),
//     B-build stores become 8 STS.64 (was 16 STS.32).
// Theory: kernel is LSU-dispatch bound (R14/R15 falsified store-wavefront
// and occupancy theories; all evidence fits MIO-issue).
// ---------------------------------------------------------------------------

#define D_MODEL 512
#define SEQ     8192
#define NST     32
#define TROW    34                    // float2 per tR row (pad)
#define BROW32  40                    // u32 per Bs row (pad: 40 mod 32 = 8)

// ---- helpers ---------------------------------------------------------------
__device__ __forceinline__ float2 cmul(float2 a, float2 b) {
    return make_float2(a.x * b.x - a.y * b.y, a.x * b.y + a.y * b.x);
}
// exp(scale*(dtAr + i*dtAi)), fp32 Cody-Waite mod-2pi (validated R7/R11/R12).
__device__ __forceinline__ float2 cexp_fast(float dtAr, float dtAi, float scale) {
    float e  = __expf(scale * dtAr);
    float mi = scale * dtAi;
    float k  = rintf(mi * 0.15915494f);
    float th = fmaf(-k, 6.2831855f, mi);
    th = fmaf(k, 1.7484556e-7f, th);
    float s, c;
    __sincosf(th, &s, &c);
    return make_float2(e * c, e * s);
}
// pack two fp32 -> half2 (v0 in low half)
__device__ __forceinline__ uint32_t pkh2(float v0, float v1) {
    __half2 h = __halves2half2(__float2half_rn(v0), __float2half_rn(v1));
    return *(uint32_t*)&h;
}
__device__ __forceinline__ void mma16816(float* acc, const uint32_t* a,
                                         const uint32_t* b) {
    asm volatile(
        "mma.sync.aligned.m16n8k16.row.col.f32.f16.f16.f32 "
        "{%0,%1,%2,%3}, {%4,%5,%6,%7}, {%8,%9}, {%0,%1,%2,%3};"
        : "+f"(acc[0]), "+f"(acc[1]), "+f"(acc[2]), "+f"(acc[3])
        : "r"(a[0]), "r"(a[1]), "r"(a[2]), "r"(a[3]), "r"(b[0]), "r"(b[1]));
}

// ---------------------------------------------------------------------------
__global__ void __launch_bounds__(128, 4)
s4d_mma_kernel(const float* __restrict__ log_dt,
               const float* __restrict__ log_A_real,
               const float* __restrict__ A_imag,
               const float2* __restrict__ C,
               float* __restrict__ out)
{
    __shared__ __align__(16) float2   tR[16 * TROW];   // 0-7: r^i ; 8-15: r^(8j)
    __shared__ __align__(16) uint32_t Bs[64 * BROW32]; // B fp16, frag word order
    __shared__ __align__(16) float4   cnA[NST];        // {dtAr, dtAi, Ccr, Cci}
    __shared__ __align__(16) float2   cnB[NST];        // r^512

    const int d   = blockIdx.x;
    const int tid = threadIdx.x;
    const int w   = tid >> 5;
    const int l   = tid & 31;
    const int q   = l & 3;
    const int g   = l >> 2;

    // ---- per-lane-n constants (lane l owns state n = l) --------------------
    int i = d * NST + l;
    float dt   = __expf(log_dt[d]);
    float Ar   = -__expf(log_A_real[i]);
    float Ai   = A_imag[i];
    float dtAr = Ar * dt;
    float dtAi = Ai * dt;

    // Warp 0 only: discretized C (2x folded), r^512, publish cn tables.
    if (w == 0) {
        float er = __expf(dtAr);
        float sn, cs;
        __sincosf(dtAi, &sn, &cs);
        float Er = er * cs - 1.0f, Ei = er * sn;
        float ar8 = Ar + 1e-8f;
        float inv = 1.0f / (ar8 * ar8 + Ai * Ai);
        float qr = (Er * ar8 + Ei * Ai) * inv;
        float qi = (Ei * ar8 - Er * Ai) * inv;
        float2 Cv = C[i];
        float Ccr = 2.0f * (Cv.x * qr - Cv.y * qi);
        float Cci = 2.0f * (Cv.x * qi + Cv.y * qr);
        cnA[l] = make_float4(dtAr, dtAi, Ccr, Cci);
        cnB[l] = cexp_fast(dtAr, dtAi, 512.0f);
    }

    // ---- Phase 1: tR tables (16 rows; warp w builds rows 4w..4w+3) ---------
#pragma unroll
    for (int rr = 0; rr < 4; rr++) {
        int row = 4 * w + rr;
        float scale = (row < 8) ? (float)row : (float)(8 * (row - 8));
        tR[row * TROW + l] = cexp_fast(dtAr, dtAi, scale);
    }
    __syncthreads();

    // ---- Phase 2: B in smem, fragment word order ---------------------------
    // Word W (k-pair index): Re n2 -> W=n2, Im n2 -> W=16+n2.
    // Frag pos(W) = 8s + 2q + h  (W = 8s + q + 4h). Build (j, j+4) together:
    // their positions are adjacent -> STS.64.
    {
        int b    = tid >> 1;
        int half = tid & 1;
        const float4* sa = (const float4*)(tR + (b & 7) * TROW);
        const float4* sb = (const float4*)(tR + (8 + (b >> 3)) * TROW);
        uint32_t* brow = Bs + b * BROW32;
#pragma unroll
        for (int jj = 0; jj < 4; jj++) {
            int j  = half * 8 + jj;      // n2 in {0..3, 8..11}
            int j2 = j + 4;
            float4 a0 = sa[j],  p0 = sb[j];
            float4 a1 = sa[j2], p1 = sb[j2];
            float2 w00 = cmul(make_float2(a0.x, a0.y), make_float2(p0.x, p0.y));
            float2 w01 = cmul(make_float2(a0.z, a0.w), make_float2(p0.z, p0.w));
            float2 w10 = cmul(make_float2(a1.x, a1.y), make_float2(p1.x, p1.y));
            float2 w11 = cmul(make_float2(a1.z, a1.w), make_float2(p1.z, p1.w));
            int posRe = 8 * (j >> 3) + 2 * (j & 3);
            uint2 re = make_uint2(pkh2(w00.x, w01.x),  pkh2(w10.x, w11.x));
            uint2 im = make_uint2(pkh2(-w00.y, -w01.y), pkh2(-w10.y, -w11.y));
            *(uint2*)(brow + posRe)      = re;   // b0/b1 sources, Re (s 0-1)
            *(uint2*)(brow + posRe + 16) = im;   // Im (s 2-3)
        }
    }

    // ---- Phase 3: A fragments in registers (constants from cn tables) ------
    // Thread A elements: rows {32w+g, +8, +16, +24}, k-cols {2q,2q+1,2q+8,
    // 2q+9}+16s -> n-set {2q,2q+1,2q+8,2q+9, +16 each}.
    uint32_t Afr[2][4][4];                   // [mtile][kstep][reg]
    const int m1 = 32 * w + g;
    const float fm = (float)(64 * m1);
#pragma unroll
    for (int p = 0; p < 4; p++) {
        int n0 = 2 * q + 8 * (p & 1) + 16 * (p >> 1);
        float4 c0  = cnA[n0];
        float4 c1  = cnA[n0 + 1];
        float4 rB  = *(const float4*)(cnB + n0);   // (r5r0,r5i0,r5r1,r5i1)
        float uRe[2][4], uIm[2][4];
        {   // e = 0
            float2 x  = cexp_fast(c0.x, c0.y, fm);
            float2 u1 = cmul(make_float2(c0.z, c0.w), x);
            float2 r5 = make_float2(rB.x, rB.y);
            float2 u2 = cmul(u1, r5);
            float2 u3 = cmul(u2, r5);
            float2 u4 = cmul(u3, r5);
            uRe[0][0] = u1.x; uIm[0][0] = u1.y;
            uRe[0][1] = u2.x; uIm[0][1] = u2.y;
            uRe[0][2] = u3.x; uIm[0][2] = u3.y;
            uRe[0][3] = u4.x; uIm[0][3] = u4.y;
        }
        {   // e = 1
            float2 x  = cexp_fast(c1.x, c1.y, fm);
            float2 u1 = cmul(make_float2(c1.z, c1.w), x);
            float2 r5 = make_float2(rB.z, rB.w);
            float2 u2 = cmul(u1, r5);
            float2 u3 = cmul(u2, r5);
            float2 u4 = cmul(u3, r5);
            uRe[1][0] = u1.x; uIm[1][0] = u1.y;
            uRe[1][1] = u2.x; uIm[1][1] = u2.y;
            uRe[1][2] = u3.x; uIm[1][2] = u3.y;
            uRe[1][3] = u4.x; uIm[1][3] = u4.y;
        }
        int s_re = p >> 1;          // kstep for Re (s=0,1); Im at s_re+2
        int ab   = 2 * (p & 1);     // reg pair offset
        Afr[0][s_re][ab + 0]     = pkh2(uRe[0][0], uRe[1][0]);
        Afr[0][s_re][ab + 1]     = pkh2(uRe[0][1], uRe[1][1]);
        Afr[1][s_re][ab + 0]     = pkh2(uRe[0][2], uRe[1][2]);
        Afr[1][s_re][ab + 1]     = pkh2(uRe[0][3], uRe[1][3]);
        Afr[0][s_re + 2][ab + 0] = pkh2(uIm[0][0], uIm[1][0]);
        Afr[0][s_re + 2][ab + 1] = pkh2(uIm[0][1], uIm[1][1]);
        Afr[1][s_re + 2][ab + 0] = pkh2(uIm[0][2], uIm[1][2]);
        Afr[1][s_re + 2][ab + 1] = pkh2(uIm[0][3], uIm[1][3]);
    }
    __syncthreads();                 // B ready

    // ---- Phase 4: MMA + direct scattered stores ----------------------------
    // b-frag: LDS.64 at word 40*(8bt+g) + 8s + 2q -> start bank (8g+2q)%32,
    // all-even distinct per half-warp phase: conflict-free.
    float* od0 = out + (size_t)d * SEQ + (size_t)(32 * w + g) * 64 + 2 * q;
#pragma unroll
    for (int bt = 0; bt < 8; bt++) {
        uint32_t Bfr[4][2];
#pragma unroll
        for (int s = 0; s < 4; s++) {
            *(uint2*)&Bfr[s][0] =
                *(const uint2*)(Bs + (8 * bt + g) * BROW32 + 8 * s + 2 * q);
        }
#pragma unroll
        for (int mt = 0; mt < 2; mt++) {
            float acc[4] = {0.f, 0.f, 0.f, 0.f};
#pragma unroll
            for (int s = 0; s < 4; s++) mma16816(acc, Afr[mt][s], Bfr[s]);
            float* o = od0 + mt * 16 * 64 + 8 * bt;
            *(float2*)(o)          = make_float2(acc[0], acc[1]);
            *(float2*)(o + 8 * 64) = make_float2(acc[2], acc[3]);
        }
    }
}

// ---------------------------------------------------------------------------
extern "C" void kernel_launch(void* const* d_in, const int* in_sizes, int n_in,
                              void* d_out, int out_size)
{
    const float*  log_dt     = (const float*)d_in[0];
    const float*  log_A_real = (const float*)d_in[1];
    const float*  A_imag     = (const float*)d_in[2];
    const float2* C          = (const float2*)d_in[3];
    float* out = (float*)d_out;

    s4d_mma_kernel<<<D_MODEL, 128>>>(log_dt, log_A_real, A_imag, C, out);
}

// round 17
// speedup vs baseline: 1.1095x; 1.0029x over previous
#include <cuda_runtime.h>
#include <cuda_fp16.h>
#include <cstdint>

// ---------------------------------------------------------------------------
// S4D kernel materialization via raw mma.sync (HMMA.16816), sm_100-safe.
//   K[d,l] = 2*Re( sum_n Cc[d,n] * exp(dtA[d,n] * l) ),  D=512, N=32, L=8192
//
// Split l = 64*m + b:  K[d,64m+b] = sum_k A[m,k]*B[b,k]  (real GEMM, K=64)
//   A[m, n] = Re(u), A[m,32+n] = Im(u),  u = 2*Cc_n * exp(dtA_n*64m)
//   B[b, n] = Re(w), B[b,32+n] = -Im(w), w = exp(dtA_n*b)
//
// Round 17 = Round 12 chassis (proven 9.6us: Bs layout with conflict-free
// LDS.32 b-frag loads, direct scattered stores) + shuffle elimination only:
//   - per-n constants {dtA, Cc, r^512} published once by warp 0 to tiny smem
//     tables; A-build reads them with 12 broadcast LDS instead of 48 SHFLs.
//   - Cc discretization chain runs in warp 0 only (was all warps).
// R16's regression was the LDS.64 bank-conflict scheme, not this change.
// ---------------------------------------------------------------------------

#define D_MODEL 512
#define SEQ     8192
#define NST     32
#define TROW    34                    // float2 per tR row (pad)
#define BROW32  36                    // u32 per Bs row (72 halves = 144 B)

// ---- helpers ---------------------------------------------------------------
__device__ __forceinline__ float2 cmul(float2 a, float2 b) {
    return make_float2(a.x * b.x - a.y * b.y, a.x * b.y + a.y * b.x);
}
// exp(scale*(dtAr + i*dtAi)), fp32 Cody-Waite mod-2pi (validated R7/R11/R12).
__device__ __forceinline__ float2 cexp_fast(float dtAr, float dtAi, float scale) {
    float e  = __expf(scale * dtAr);
    float mi = scale * dtAi;
    float k  = rintf(mi * 0.15915494f);
    float th = fmaf(-k, 6.2831855f, mi);
    th = fmaf(k, 1.7484556e-7f, th);
    float s, c;
    __sincosf(th, &s, &c);
    return make_float2(e * c, e * s);
}
// pack two fp32 -> half2 (v0 in low half)
__device__ __forceinline__ uint32_t pkh2(float v0, float v1) {
    __half2 h = __halves2half2(__float2half_rn(v0), __float2half_rn(v1));
    return *(uint32_t*)&h;
}
__device__ __forceinline__ void mma16816(float* acc, const uint32_t* a,
                                         const uint32_t* b) {
    asm volatile(
        "mma.sync.aligned.m16n8k16.row.col.f32.f16.f16.f32 "
        "{%0,%1,%2,%3}, {%4,%5,%6,%7}, {%8,%9}, {%0,%1,%2,%3};"
        : "+f"(acc[0]), "+f"(acc[1]), "+f"(acc[2]), "+f"(acc[3])
        : "r"(a[0]), "r"(a[1]), "r"(a[2]), "r"(a[3]), "r"(b[0]), "r"(b[1]));
}

// ---------------------------------------------------------------------------
__global__ void __launch_bounds__(128, 4)
s4d_mma_kernel(const float* __restrict__ log_dt,
               const float* __restrict__ log_A_real,
               const float* __restrict__ A_imag,
               const float2* __restrict__ C,
               float* __restrict__ out)
{
    __shared__ __align__(16) float2   tR[16 * TROW];   // 0-7: r^i ; 8-15: r^(8j)
    __shared__ __align__(16) uint32_t Bs[64 * BROW32]; // B fp16 [b][72 halves]
    __shared__ __align__(16) float4   cnA[NST];        // {dtAr, dtAi, Ccr, Cci}
    __shared__ __align__(16) float2   cnB[NST];        // r^512

    const int d   = blockIdx.x;
    const int tid = threadIdx.x;
    const int w   = tid >> 5;
    const int l   = tid & 31;
    const int q   = l & 3;
    const int g   = l >> 2;

    // ---- per-lane-n constants (lane l owns state n = l) --------------------
    int i = d * NST + l;
    float dt   = __expf(log_dt[d]);
    float Ar   = -__expf(log_A_real[i]);
    float Ai   = A_imag[i];
    float dtAr = Ar * dt;
    float dtAi = Ai * dt;

    // Warp 0 only: discretized C (2x folded), r^512, publish cn tables.
    if (w == 0) {
        float er = __expf(dtAr);
        float sn, cs;
        __sincosf(dtAi, &sn, &cs);
        float Er = er * cs - 1.0f, Ei = er * sn;
        float ar8 = Ar + 1e-8f;
        float inv = 1.0f / (ar8 * ar8 + Ai * Ai);
        float qr = (Er * ar8 + Ei * Ai) * inv;
        float qi = (Ei * ar8 - Er * Ai) * inv;
        float2 Cv = C[i];
        float Ccr = 2.0f * (Cv.x * qr - Cv.y * qi);
        float Cci = 2.0f * (Cv.x * qi + Cv.y * qr);
        cnA[l] = make_float4(dtAr, dtAi, Ccr, Cci);
        cnB[l] = cexp_fast(dtAr, dtAi, 512.0f);
    }

    // ---- Phase 1: tR tables (16 rows; warp w builds rows 4w..4w+3) ---------
#pragma unroll
    for (int rr = 0; rr < 4; rr++) {
        int row = 4 * w + rr;
        float scale = (row < 8) ? (float)row : (float)(8 * (row - 8));
        tR[row * TROW + l] = cexp_fast(dtAr, dtAi, scale);
    }
    __syncthreads();

    // ---- Phase 2: B in smem (b = tid>>1, 8 n2-units each) — R12 verbatim ---
    {
        int b  = tid >> 1;
        int h0 = (tid & 1) * 8;
        const float4* sa = (const float4*)(tR + (b & 7) * TROW);
        const float4* sb = (const float4*)(tR + (8 + (b >> 3)) * TROW);
#pragma unroll
        for (int n2i = 0; n2i < 8; n2i++) {
            int n2 = h0 + n2i;
            float4 a = sa[n2], p = sb[n2];
            float2 w0 = cmul(make_float2(a.x, a.y), make_float2(p.x, p.y));
            float2 w1 = cmul(make_float2(a.z, a.w), make_float2(p.z, p.w));
            Bs[b * BROW32 + n2]      = pkh2(w0.x, w1.x);    // Re  (k = 2n2,2n2+1)
            Bs[b * BROW32 + 16 + n2] = pkh2(-w0.y, -w1.y);  // -Im (k = 32+2n2,..)
        }
    }

    // ---- Phase 3: A fragments in registers (constants from cn tables) ------
    // Thread A elements: rows {32w+g, +8, +16, +24}, k-cols {2q,2q+1,2q+8,
    // 2q+9}+16s -> n-set {2q,2q+1,2q+8,2q+9, +16 each}.
    uint32_t Afr[2][4][4];                   // [mtile][kstep][reg]
    const int m1 = 32 * w + g;
    const float fm = (float)(64 * m1);
#pragma unroll
    for (int p = 0; p < 4; p++) {
        int n0 = 2 * q + 8 * (p & 1) + 16 * (p >> 1);
        float4 c0 = cnA[n0];
        float4 c1 = cnA[n0 + 1];
        float4 rB = *(const float4*)(cnB + n0);   // (r5r0,r5i0,r5r1,r5i1)
        float uRe[2][4], uIm[2][4];
        {   // e = 0
            float2 x  = cexp_fast(c0.x, c0.y, fm);
            float2 u1 = cmul(make_float2(c0.z, c0.w), x);
            float2 r5 = make_float2(rB.x, rB.y);
            float2 u2 = cmul(u1, r5);
            float2 u3 = cmul(u2, r5);
            float2 u4 = cmul(u3, r5);
            uRe[0][0] = u1.x; uIm[0][0] = u1.y;
            uRe[0][1] = u2.x; uIm[0][1] = u2.y;
            uRe[0][2] = u3.x; uIm[0][2] = u3.y;
            uRe[0][3] = u4.x; uIm[0][3] = u4.y;
        }
        {   // e = 1
            float2 x  = cexp_fast(c1.x, c1.y, fm);
            float2 u1 = cmul(make_float2(c1.z, c1.w), x);
            float2 r5 = make_float2(rB.z, rB.w);
            float2 u2 = cmul(u1, r5);
            float2 u3 = cmul(u2, r5);
            float2 u4 = cmul(u3, r5);
            uRe[1][0] = u1.x; uIm[1][0] = u1.y;
            uRe[1][1] = u2.x; uIm[1][1] = u2.y;
            uRe[1][2] = u3.x; uIm[1][2] = u3.y;
            uRe[1][3] = u4.x; uIm[1][3] = u4.y;
        }
        int s_re = p >> 1;          // kstep for Re (s=0,1); Im at s_re+2
        int ab   = 2 * (p & 1);     // reg pair offset
        Afr[0][s_re][ab + 0]     = pkh2(uRe[0][0], uRe[1][0]);
        Afr[0][s_re][ab + 1]     = pkh2(uRe[0][1], uRe[1][1]);
        Afr[1][s_re][ab + 0]     = pkh2(uRe[0][2], uRe[1][2]);
        Afr[1][s_re][ab + 1]     = pkh2(uRe[0][3], uRe[1][3]);
        Afr[0][s_re + 2][ab + 0] = pkh2(uIm[0][0], uIm[1][0]);
        Afr[0][s_re + 2][ab + 1] = pkh2(uIm[0][1], uIm[1][1]);
        Afr[1][s_re + 2][ab + 0] = pkh2(uIm[0][2], uIm[1][2]);
        Afr[1][s_re + 2][ab + 1] = pkh2(uIm[0][3], uIm[1][3]);
    }
    __syncthreads();                 // B ready

    // ---- Phase 4: MMA + direct scattered stores — R12 verbatim -------------
    // b-frag LDS word = 36*(8bt+g) + 8s + q -> bank (4g+q+8s)%32: permutation,
    // conflict-free.
    float* od0 = out + (size_t)d * SEQ + (size_t)(32 * w + g) * 64 + 2 * q;
#pragma unroll
    for (int bt = 0; bt < 8; bt++) {
        uint32_t Bfr[4][2];
#pragma unroll
        for (int s = 0; s < 4; s++) {
            const uint32_t* brow = Bs + (8 * bt + g) * BROW32 + 8 * s + q;
            Bfr[s][0] = brow[0];
            Bfr[s][1] = brow[4];
        }
#pragma unroll
        for (int mt = 0; mt < 2; mt++) {
            float acc[4] = {0.f, 0.f, 0.f, 0.f};
#pragma unroll
            for (int s = 0; s < 4; s++) mma16816(acc, Afr[mt][s], Bfr[s]);
            float* o = od0 + mt * 16 * 64 + 8 * bt;
            *(float2*)(o)          = make_float2(acc[0], acc[1]);
            *(float2*)(o + 8 * 64) = make_float2(acc[2], acc[3]);
        }
    }
}

// ---------------------------------------------------------------------------
extern "C" void kernel_launch(void* const* d_in, const int* in_sizes, int n_in,
                              void* d_out, int out_size)
{
    const float*  log_dt     = (const float*)d_in[0];
    const float*  log_A_real = (const float*)d_in[1];
    const float*  A_imag     = (const float*)d_in[2];
    const float2* C          = (const float2*)d_in[3];
    float* out = (float*)d_out;

    s4d_mma_kernel<<<D_MODEL, 128>>>(log_dt, log_A_real, A_imag, C, out);
}